// round 14
// baseline (speedup 1.0000x reference)
#include <cuda_runtime.h>
#include <math.h>
#include <stdint.h>

#define BB 8
#define CH 64
#define HH 256
#define WW 256
#define HW 65536

typedef unsigned long long u64;

__device__ __forceinline__ u64 pk2(float lo, float hi){ u64 r; asm("mov.b64 %0,{%1,%2};" : "=l"(r) : "f"(lo), "f"(hi)); return r; }
__device__ __forceinline__ u64 splat2(float v){ u64 r; asm("mov.b64 %0,{%1,%1};" : "=l"(r) : "f"(v)); return r; }
__device__ __forceinline__ float2 upk2(u64 a){ float2 f; asm("mov.b64 {%0,%1},%2;" : "=f"(f.x), "=f"(f.y) : "l"(a)); return f; }
__device__ __forceinline__ u64 f2fma(u64 a, u64 b, u64 c){ u64 d; asm("fma.rn.f32x2 %0,%1,%2,%3;" : "=l"(d) : "l"(a), "l"(b), "l"(c)); return d; }

__device__ __forceinline__ float fast_tanh(float x){
    float e, r;
    asm("ex2.approx.f32 %0, %1;" : "=f"(e) : "f"(x * 2.8853900817779268f));
    asm("rcp.approx.f32 %0, %1;" : "=f"(r) : "f"(e + 1.0f));
    return fmaf(-2.0f, r, 1.0f);
}
__device__ __forceinline__ float tanh_rcp(float x){
    float e, r;
    asm("ex2.approx.f32 %0, %1;" : "=f"(e) : "f"(x * 2.8853900817779268f));
    asm("rcp.approx.f32 %0, %1;" : "=f"(r) : "f"(e + 1.0f));
    return r;
}

// Scratch
__device__ float g_v [BB*CH*64];
__device__ float g_gA[BB*CH*64];
__device__ float g_wre[32*4096];
__device__ float g_wim[32*4096];

// ---------------------------------------------------------------------------
// K0: repack spectral weights. Unchanged.
// ---------------------------------------------------------------------------
__global__ void k_repack(const float* __restrict__ w1r, const float* __restrict__ w1i,
                         const float* __restrict__ w2r, const float* __restrict__ w2i)
{
    int s = blockIdx.x;
    int kxi = s >> 2, ky = s & 3;
    const float* srcr = (kxi < 4) ? w1r : w2r;
    const float* srci = (kxi < 4) ? w1i : w2i;
    int kk = (kxi & 3) * 4 + ky;
    for (int idx = threadIdx.x; idx < 4096; idx += blockDim.x) {
        g_wre[s*4096 + idx] = srcr[idx*16 + kk];
        g_wim[s*4096 + idx] = srci[idx*16 + kk];
    }
}

// ---------------------------------------------------------------------------
// K2: projection, 2 channels per block, scalar. Unchanged.
// ---------------------------------------------------------------------------
__global__ void __launch_bounds__(256) k_project(
    const float* __restrict__ x,
    const float* __restrict__ ew,
    const float* __restrict__ eb)
{
    __shared__ float ph[256][8];
    __shared__ float red[8][64];
    __shared__ float4 wenc2[2];
    int w = threadIdx.x, cg = blockIdx.x, b = blockIdx.y;
    int c0 = cg * 2;
    if (w < 2) wenc2[w] = make_float4(ew[3*(c0+w)], ew[3*(c0+w)+1], ew[3*(c0+w)+2], eb[c0+w]);

    float a = 6.28318530717958647692f * (1.0f/256.0f) * (float)w;
    float c1, s1; sincosf(a, &s1, &c1);
    float c2 = c1*c1 - s1*s1,  s2 = 2.f*s1*c1;
    float c3 = c2*c1 - s2*s1,  s3 = s2*c1 + c2*s1;
    float c4 = c2*c2 - s2*s2,  s4 = 2.f*s2*c2;
    ph[w][0]=c1; ph[w][1]=s1; ph[w][2]=c2; ph[w][3]=s2;
    ph[w][4]=c3; ph[w][5]=s3; ph[w][6]=c4; ph[w][7]=s4;
    __syncthreads();

    float4 weA = wenc2[0], weB = wenc2[1];
    const float* xp = x + (b*3)*HW + w;
    float A0[2]={0,0}, AR1[2]={0,0}, B1[2]={0,0}, AR2[2]={0,0}, B2[2]={0,0},
          AR3[2]={0,0}, B3[2]={0,0}, AR4[2]={0,0}, B4[2]={0,0};
    #pragma unroll 2
    for (int hh = 0; hh < 256; hh++) {
        float x0 = xp[hh*256], x1 = xp[hh*256 + HW], x2 = xp[hh*256 + 2*HW];
        float4 p0 = *(const float4*)&ph[hh][0];
        float4 p1 = *(const float4*)&ph[hh][4];
        {
            float pre = fmaf(weA.x, x0, fmaf(weA.y, x1, fmaf(weA.z, x2, weA.w)));
            float v = fmaf(-4.f, tanh_rcp(pre), 2.f);
            A0[0] += v;
            AR1[0] = fmaf(v, p0.x, AR1[0]);  B1[0] = fmaf(v, p0.y, B1[0]);
            AR2[0] = fmaf(v, p0.z, AR2[0]);  B2[0] = fmaf(v, p0.w, B2[0]);
            AR3[0] = fmaf(v, p1.x, AR3[0]);  B3[0] = fmaf(v, p1.y, B3[0]);
            AR4[0] = fmaf(v, p1.z, AR4[0]);  B4[0] = fmaf(v, p1.w, B4[0]);
        }
        {
            float pre = fmaf(weB.x, x0, fmaf(weB.y, x1, fmaf(weB.z, x2, weB.w)));
            float v = fmaf(-4.f, tanh_rcp(pre), 2.f);
            A0[1] += v;
            AR1[1] = fmaf(v, p0.x, AR1[1]);  B1[1] = fmaf(v, p0.y, B1[1]);
            AR2[1] = fmaf(v, p0.z, AR2[1]);  B2[1] = fmaf(v, p0.w, B2[1]);
            AR3[1] = fmaf(v, p1.x, AR3[1]);  B3[1] = fmaf(v, p1.y, B3[1]);
            AR4[1] = fmaf(v, p1.z, AR4[1]);  B4[1] = fmaf(v, p1.w, B4[1]);
        }
    }

    float cyk[4] = {1.f, c1, c2, c3};
    float syk[4] = {0.f, s1, s2, s3};
    int lane = w & 31, wid = w >> 5;

    #pragma unroll
    for (int ch = 0; ch < 2; ch++) {
        float crr[8] = {A0[ch],  AR1[ch], AR2[ch], AR3[ch], AR4[ch], AR3[ch], AR2[ch], AR1[ch]};
        float cii[8] = {0.f, -B1[ch], -B2[ch], -B3[ch],  B4[ch],  B3[ch],  B2[ch],  B1[ch]};
        #pragma unroll
        for (int kxi = 0; kxi < 8; kxi++) {
            #pragma unroll
            for (int ky = 0; ky < 4; ky++) {
                float re = crr[kxi]*cyk[ky] + cii[kxi]*syk[ky];
                float im = cii[kxi]*cyk[ky] - crr[kxi]*syk[ky];
                #pragma unroll
                for (int o = 16; o > 0; o >>= 1) {
                    re += __shfl_xor_sync(0xffffffffu, re, o);
                    im += __shfl_xor_sync(0xffffffffu, im, o);
                }
                if (lane == 0) {
                    red[wid][(kxi*4+ky)*2    ] = re;
                    red[wid][(kxi*4+ky)*2 + 1] = im;
                }
            }
        }
        __syncthreads();
        if (w < 64) {
            float s = 0.f;
            #pragma unroll
            for (int q = 0; q < 8; q++) s += red[q][w];
            g_v[(b*CH + c0 + ch)*64 + w] = s;
        }
        __syncthreads();
    }
}

// ---------------------------------------------------------------------------
// K3: ALL 6 mode-space iterations fused. Unchanged.
// ---------------------------------------------------------------------------
__global__ void __launch_bounds__(128) k_mix6()
{
    extern __shared__ float smw[];
    float* swr = smw;
    float* swi = smw + 8192;
    __shared__ float vr[2][64], vi[2][64], gr[2][64], gi[2][64], fr[2][64], fi[2][64];

    int g = blockIdx.x, b = blockIdx.y, tid = threadIdx.x;
    int s0, s1 = -1, tmode;
    if (g < 24)      { int kxi=g/3, ky=g%3+1; s0=kxi*4+ky; tmode=0; }
    else if (g==24)  { s0=0;           tmode=1; }
    else if (g==25)  { s0=16;          tmode=2; }
    else if (g==26)  { s0=4;  s1=28;   tmode=3; }
    else if (g==27)  { s0=8;  s1=24;   tmode=3; }
    else             { s0=12; s1=20;   tmode=3; }
    int nsl = (s1 >= 0) ? 2 : 1;

    for (int q = 0; q < nsl; q++) {
        int s = q ? s1 : s0;
        for (int idx = tid; idx < 4096; idx += 128) {
            swr[q*4096 + idx] = g_wre[s*4096 + idx];
            swi[q*4096 + idx] = g_wim[s*4096 + idx];
        }
    }
    int sl = tid >> 6, o = tid & 63;
    if (sl < nsl) {
        int s = sl ? s1 : s0;
        int base = (b*64 + o)*64 + s*2;
        vr[sl][o] = g_v[base]; vi[sl][o] = g_v[base+1];
    }
    __syncthreads();

    for (int it = 0; it < 6; it++) {
        if (sl < nsl) {
            float tr = 0.f, ti = 0.f;
            if (it > 0) {
                float grv = gr[sl][o], giv = gi[sl][o];
                if      (tmode == 0) { tr = grv;       ti = giv; }
                else if (tmode == 1) { tr = grv;       ti = 0.f; }
                else if (tmode == 2) { tr = 0.5f*grv;  ti = 0.5f*giv; }
                else { tr = 0.5f*(grv + gr[1-sl][o]);  ti = 0.5f*(giv - gi[1-sl][o]); }
            }
            fr[sl][o] = vr[sl][o] + tr;
            fi[sl][o] = vi[sl][o] + ti;
        }
        __syncthreads();
        float accr = 0.f, acci = 0.f;
        if (sl < nsl) {
            const float* wrp = swr + sl*4096;
            const float* wip = swi + sl*4096;
            #pragma unroll 8
            for (int i = 0; i < 64; i++) {
                float w_r = wrp[i*64 + o], w_i = wip[i*64 + o];
                float f_r = fr[sl][i],     f_i = fi[sl][i];
                accr = fmaf(f_r, w_r, accr); accr = fmaf(-f_i, w_i, accr);
                acci = fmaf(f_r, w_i, acci); acci = fmaf( f_i, w_r, acci);
            }
        }
        __syncthreads();
        if (sl < nsl) {
            float g0r = it ? gr[sl][o] : 0.f;
            float g0i = it ? gi[sl][o] : 0.f;
            gr[sl][o] = g0r + accr;
            gi[sl][o] = g0i + acci;
        }
        __syncthreads();
    }

    if (sl < nsl) {
        int s = sl ? s1 : s0;
        int base = (b*64 + o)*64 + s*2;
        g_gA[base]   = gr[sl][o];
        g_gA[base+1] = gi[sl][o];
    }
}

// ---------------------------------------------------------------------------
// K5: recon-once + reshaped GEMV (4 px x 16 outputs per thread).
// Phase 1: recon into hvs[c][wv] (u64 row-pairs). Phase 2: thread (wq, og)
// handles cols (2wq, 2wq+1) x rows (h0,h1), outputs og*16..+15.
// Per c: 1 hvs LDS.128 + 4 weight LDS.128 + 32 FFMA2 -> FMA-bound.
// 4-way og partial reduction in smem.
// ---------------------------------------------------------------------------
#define HVS_SMEM (64*128*8)

__global__ void __launch_bounds__(256, 2) k_final(
    const float* __restrict__ x,
    const float* __restrict__ ew, const float* __restrict__ eb,
    const float* __restrict__ d1w, const float* __restrict__ d1b,
    const float* __restrict__ d2w, const float* __restrict__ d2b,
    float* __restrict__ out)
{
    extern __shared__ u64 hvs[];     // [64][128] u64 = 64 KB dynamic
    __shared__ u64 zp[64*8];
    __shared__ float gm[4096];
    __shared__ float4 wenc[64];
    __shared__ u64 wp[64*32];
    __shared__ u64 b1p[32], w2p[32];
    __shared__ float ps[4][256];     // og partials: [og][row*128 + col]

    int t = threadIdx.x, b = blockIdx.y;
    int hpair = blockIdx.x & 127, wtile = blockIdx.x >> 7;
    int h0 = hpair*2, h1 = h0 + 1;

    for (int idx = t; idx < 2048; idx += 256) {
        int c = idx & 63, op = idx >> 6;
        wp[c*32 + op] = pk2(d1w[(2*op)*64 + c], d1w[(2*op+1)*64 + c]);
    }
    if (t < 32) {
        b1p[t] = pk2(d1b[2*t], d1b[2*t+1]);
        w2p[t] = pk2(d2w[2*t], d2w[2*t+1]);
    }
    if (t < 64) {
        const float K = 2.8853900817779268f;
        wenc[t] = make_float4(K*ew[3*t], K*ew[3*t+1], K*ew[3*t+2], K*eb[t]);
    }
    {
        const float4* gsrc = (const float4*)(g_gA + b*4096);
        float4* gdst = (float4*)gm;
        #pragma unroll
        for (int i = 0; i < 4; i++) gdst[t + i*256] = gsrc[t + i*256];
    }
    __syncthreads();

    // in-block Z for both rows: thread (c = t>>2, ky = t&3)
    {
        int c = t >> 2, ky = t & 3;
        float zrA = 0.f, ziA = 0.f, zrB = 0.f, ziB = 0.f;
        float aA = 6.28318530717958647692f * (1.0f/256.0f) * (float)h0;
        float c1A, s1A; sincosf(aA, &s1A, &c1A);
        float c2A = c1A*c1A - s1A*s1A,  s2A = 2.f*s1A*c1A;
        float c3A = c2A*c1A - s2A*s1A,  s3A = s2A*c1A + c2A*s1A;
        float c4A = c2A*c2A - s2A*s2A,  s4A = 2.f*s2A*c2A;
        float pcA[8] = {1.f, c1A, c2A, c3A,  c4A,  c3A,  c2A,  c1A};
        float psA[8] = {0.f, s1A, s2A, s3A, -s4A, -s3A, -s2A, -s1A};
        float aB = 6.28318530717958647692f * (1.0f/256.0f) * (float)h1;
        float c1B, s1B; sincosf(aB, &s1B, &c1B);
        float c2B = c1B*c1B - s1B*s1B,  s2B = 2.f*s1B*c1B;
        float c3B = c2B*c1B - s2B*s1B,  s3B = s2B*c1B + c2B*s1B;
        float c4B = c2B*c2B - s2B*s2B,  s4B = 2.f*s2B*c2B;
        float pcB[8] = {1.f, c1B, c2B, c3B,  c4B,  c3B,  c2B,  c1B};
        float psB[8] = {0.f, s1B, s2B, s3B, -s4B, -s3B, -s2B, -s1B};
        #pragma unroll
        for (int kxi = 0; kxi < 8; kxi++) {
            float grv = gm[c*64 + kxi*8 + ky*2];
            float giv = gm[c*64 + kxi*8 + ky*2 + 1];
            zrA += grv*pcA[kxi] - giv*psA[kxi];
            ziA += grv*psA[kxi] + giv*pcA[kxi];
            zrB += grv*pcB[kxi] - giv*psB[kxi];
            ziB += grv*psB[kxi] + giv*pcB[kxi];
        }
        if (ky == 0) {
            zp[c*8]     = pk2(zrA*(1.f/131072.f) + 2.f, zrB*(1.f/131072.f) + 2.f);
            zp[c*8 + 7] = 0ull;
        } else {
            zp[c*8 + ky*2 - 1] = pk2( zrA*(1.f/65536.f),  zrB*(1.f/65536.f));
            zp[c*8 + ky*2]     = pk2(-ziA*(1.f/65536.f), -ziB*(1.f/65536.f));
        }
    }
    __syncthreads();

    // --- Phase 1: recon into hvs. Thread: wv = t&127 fixed, c = (t>>7) + 2k.
    {
        int wv = t & 127;
        int coff = t >> 7;
        int w = wtile*128 + wv;

        float a = 6.28318530717958647692f * (1.0f/256.0f) * (float)w;
        float cy1, sy1; sincosf(a, &sy1, &cy1);
        float cy2 = cy1*cy1 - sy1*sy1, sy2 = 2.f*sy1*cy1;
        float cy3 = cy2*cy1 - sy2*sy1, sy3 = sy2*cy1 + cy2*sy1;
        u64 C1 = splat2(cy1), S1 = splat2(sy1);
        u64 C2 = splat2(cy2), S2 = splat2(sy2);
        u64 C3 = splat2(cy3), S3 = splat2(sy3);
        u64 M4 = splat2(-4.f);

        const float* xpA = x + (b*3)*HW + h0*WW + w;
        float x0A = xpA[0],    x0B = xpA[WW];
        float x1A = xpA[HW],   x1B = xpA[HW+WW];
        float x2A = xpA[2*HW], x2B = xpA[2*HW+WW];

        const ulonglong2* zrow2 = (const ulonglong2*)zp;
        #pragma unroll 8
        for (int k = 0; k < 32; k++) {
            int c = coff + 2*k;
            float4 we = wenc[c];
            float preA = fmaf(we.x, x0A, fmaf(we.y, x1A, fmaf(we.z, x2A, we.w)));
            float preB = fmaf(we.x, x0B, fmaf(we.y, x1B, fmaf(we.z, x2B, we.w)));
            float eA, rA, eB, rB;
            asm("ex2.approx.f32 %0, %1;" : "=f"(eA) : "f"(preA));
            asm("ex2.approx.f32 %0, %1;" : "=f"(eB) : "f"(preB));
            asm("rcp.approx.f32 %0, %1;" : "=f"(rA) : "f"(eA + 1.0f));
            asm("rcp.approx.f32 %0, %1;" : "=f"(rB) : "f"(eB + 1.0f));
            ulonglong2 z01 = zrow2[c*4], z23 = zrow2[c*4+1], z45 = zrow2[c*4+2], z67 = zrow2[c*4+3];
            u64 hv2 = f2fma(pk2(rA, rB), M4, z01.x);
            hv2 = f2fma(z01.y, C1, hv2);
            hv2 = f2fma(z23.x, S1, hv2);
            hv2 = f2fma(z23.y, C2, hv2);
            hv2 = f2fma(z45.x, S2, hv2);
            hv2 = f2fma(z45.y, C3, hv2);
            hv2 = f2fma(z67.x, S3, hv2);
            hvs[c*128 + wv] = hv2;
        }
    }
    __syncthreads();

    // --- Phase 2: GEMV. Thread (wq = t>>2, og = t&3). ---
    int og = t & 3, wq = t >> 2;

    u64 a00[8], a01[8], a10[8], a11[8];   // [col][pair] for rows packed? ->
    // a00: col0 rowA, a01: col0 rowB, a10: col1 rowA, a11: col1 rowB
    #pragma unroll
    for (int k = 0; k < 8; k++) {
        u64 bb = b1p[og*8 + k];
        a00[k] = bb; a01[k] = bb; a10[k] = bb; a11[k] = bb;
    }

    const ulonglong2* wbase = (const ulonglong2*)wp + og*4;
    #pragma unroll 4
    for (int c = 0; c < 64; c++) {
        ulonglong2 h2 = *(const ulonglong2*)&hvs[c*128 + 2*wq];
        float2 hva = upk2(h2.x);   // col0: (rowA, rowB)
        float2 hvb = upk2(h2.y);   // col1: (rowA, rowB)
        u64 h00 = splat2(hva.x), h01 = splat2(hva.y);
        u64 h10 = splat2(hvb.x), h11 = splat2(hvb.y);
        const ulonglong2* wr = wbase + c*16;
        #pragma unroll
        for (int k2 = 0; k2 < 4; k2++) {
            ulonglong2 wv2 = wr[k2];
            a00[k2*2]   = f2fma(h00, wv2.x, a00[k2*2]);
            a00[k2*2+1] = f2fma(h00, wv2.y, a00[k2*2+1]);
            a01[k2*2]   = f2fma(h01, wv2.x, a01[k2*2]);
            a01[k2*2+1] = f2fma(h01, wv2.y, a01[k2*2+1]);
            a10[k2*2]   = f2fma(h10, wv2.x, a10[k2*2]);
            a10[k2*2+1] = f2fma(h10, wv2.y, a10[k2*2+1]);
            a11[k2*2]   = f2fma(h11, wv2.x, a11[k2*2]);
            a11[k2*2+1] = f2fma(h11, wv2.y, a11[k2*2+1]);
        }
    }

    // epilogue: tanh + dot with w2 for the og slice, 4 pixels
    u64 o00 = 0ull, o01 = 0ull, o10 = 0ull, o11 = 0ull;
    #pragma unroll
    for (int k = 0; k < 8; k++) {
        u64 w2v = w2p[og*8 + k];
        float2 v00 = upk2(a00[k]), v01 = upk2(a01[k]);
        float2 v10 = upk2(a10[k]), v11 = upk2(a11[k]);
        o00 = f2fma(pk2(fast_tanh(v00.x), fast_tanh(v00.y)), w2v, o00);
        o01 = f2fma(pk2(fast_tanh(v01.x), fast_tanh(v01.y)), w2v, o01);
        o10 = f2fma(pk2(fast_tanh(v10.x), fast_tanh(v10.y)), w2v, o10);
        o11 = f2fma(pk2(fast_tanh(v11.x), fast_tanh(v11.y)), w2v, o11);
    }
    {
        float2 s00 = upk2(o00), s01 = upk2(o01), s10 = upk2(o10), s11 = upk2(o11);
        int col0 = 2*wq, col1 = 2*wq + 1;
        ps[og][0*128 + col0] = s00.x + s00.y;   // rowA col0
        ps[og][1*128 + col0] = s01.x + s01.y;   // rowB col0
        ps[og][0*128 + col1] = s10.x + s10.y;   // rowA col1
        ps[og][1*128 + col1] = s11.x + s11.y;   // rowB col1
    }
    __syncthreads();

    {
        int r = t >> 7, col = t & 127;
        float v = ps[0][r*128 + col] + ps[1][r*128 + col]
                + ps[2][r*128 + col] + ps[3][r*128 + col] + d2b[0];
        out[b*HW + (h0 + r)*WW + wtile*128 + col] = v;
    }
}

extern "C" void kernel_launch(void* const* d_in, const int* in_sizes, int n_in,
                              void* d_out, int out_size)
{
    const float* x   = (const float*)d_in[0];
    const float* ew  = (const float*)d_in[1];
    const float* eb  = (const float*)d_in[2];
    const float* d1w = (const float*)d_in[3];
    const float* d1b = (const float*)d_in[4];
    const float* d2w = (const float*)d_in[5];
    const float* d2b = (const float*)d_in[6];
    const float* w1r = (const float*)d_in[7];
    const float* w1i = (const float*)d_in[8];
    const float* w2r = (const float*)d_in[9];
    const float* w2i = (const float*)d_in[10];
    float* out = (float*)d_out;

    cudaFuncSetAttribute(k_mix6, cudaFuncAttributeMaxDynamicSharedMemorySize, 65536);
    cudaFuncSetAttribute(k_final, cudaFuncAttributeMaxDynamicSharedMemorySize, HVS_SMEM);

    k_repack<<<32, 256>>>(w1r, w1i, w2r, w2i);
    k_project<<<dim3(32, 8), 256>>>(x, ew, eb);
    k_mix6<<<dim3(29, 8), 128, 65536>>>();
    k_final<<<dim3(256, 8), 256, HVS_SMEM>>>(x, ew, eb, d1w, d1b, d2w, d2b, out);
}

// round 15
// speedup vs baseline: 1.0654x; 1.0654x over previous
#include <cuda_runtime.h>
#include <math.h>
#include <stdint.h>

#define BB 8
#define CH 64
#define HH 256
#define WW 256
#define HW 65536

typedef unsigned long long u64;

__device__ __forceinline__ u64 pk2(float lo, float hi){ u64 r; asm("mov.b64 %0,{%1,%2};" : "=l"(r) : "f"(lo), "f"(hi)); return r; }
__device__ __forceinline__ u64 splat2(float v){ u64 r; asm("mov.b64 %0,{%1,%1};" : "=l"(r) : "f"(v)); return r; }
__device__ __forceinline__ float2 upk2(u64 a){ float2 f; asm("mov.b64 {%0,%1},%2;" : "=f"(f.x), "=f"(f.y) : "l"(a)); return f; }
__device__ __forceinline__ u64 f2fma(u64 a, u64 b, u64 c){ u64 d; asm("fma.rn.f32x2 %0,%1,%2,%3;" : "=l"(d) : "l"(a), "l"(b), "l"(c)); return d; }

__device__ __forceinline__ float fast_tanh(float x){
    float e, r;
    asm("ex2.approx.f32 %0, %1;" : "=f"(e) : "f"(x * 2.8853900817779268f));
    asm("rcp.approx.f32 %0, %1;" : "=f"(r) : "f"(e + 1.0f));
    return fmaf(-2.0f, r, 1.0f);
}
__device__ __forceinline__ float tanh_rcp(float x){
    float e, r;
    asm("ex2.approx.f32 %0, %1;" : "=f"(e) : "f"(x * 2.8853900817779268f));
    asm("rcp.approx.f32 %0, %1;" : "=f"(r) : "f"(e + 1.0f));
    return r;
}

// Scratch
__device__ float g_v [BB*CH*64];
__device__ float g_gA[BB*CH*64];
__device__ float g_wre[32*4096];
__device__ float g_wim[32*4096];

// ---------------------------------------------------------------------------
// K0: repack spectral weights. Unchanged.
// ---------------------------------------------------------------------------
__global__ void k_repack(const float* __restrict__ w1r, const float* __restrict__ w1i,
                         const float* __restrict__ w2r, const float* __restrict__ w2i)
{
    int s = blockIdx.x;
    int kxi = s >> 2, ky = s & 3;
    const float* srcr = (kxi < 4) ? w1r : w2r;
    const float* srci = (kxi < 4) ? w1i : w2i;
    int kk = (kxi & 3) * 4 + ky;
    for (int idx = threadIdx.x; idx < 4096; idx += blockDim.x) {
        g_wre[s*4096 + idx] = srcr[idx*16 + kk];
        g_wim[s*4096 + idx] = srci[idx*16 + kk];
    }
}

// ---------------------------------------------------------------------------
// K2: projection, 4 CHANNELS per block (x LDG amortized 4x).
// grid = (16, 8), block = 256.
// ---------------------------------------------------------------------------
__global__ void __launch_bounds__(256) k_project(
    const float* __restrict__ x,
    const float* __restrict__ ew,
    const float* __restrict__ eb)
{
    __shared__ float ph[256][8];
    __shared__ float red[8][64];
    __shared__ float4 wenc4[4];
    int w = threadIdx.x, cg = blockIdx.x, b = blockIdx.y;
    int c0 = cg * 4;
    if (w < 4) wenc4[w] = make_float4(ew[3*(c0+w)], ew[3*(c0+w)+1], ew[3*(c0+w)+2], eb[c0+w]);

    float a = 6.28318530717958647692f * (1.0f/256.0f) * (float)w;
    float c1, s1; sincosf(a, &s1, &c1);
    float c2 = c1*c1 - s1*s1,  s2 = 2.f*s1*c1;
    float c3 = c2*c1 - s2*s1,  s3 = s2*c1 + c2*s1;
    float c4 = c2*c2 - s2*s2,  s4 = 2.f*s2*c2;
    ph[w][0]=c1; ph[w][1]=s1; ph[w][2]=c2; ph[w][3]=s2;
    ph[w][4]=c3; ph[w][5]=s3; ph[w][6]=c4; ph[w][7]=s4;
    __syncthreads();

    float4 we0 = wenc4[0], we1 = wenc4[1], we2c = wenc4[2], we3 = wenc4[3];
    const float* xp = x + (b*3)*HW + w;
    float A0[4]={0,0,0,0}, AR1[4]={0,0,0,0}, B1[4]={0,0,0,0}, AR2[4]={0,0,0,0},
          B2[4]={0,0,0,0}, AR3[4]={0,0,0,0}, B3[4]={0,0,0,0}, AR4[4]={0,0,0,0},
          B4[4]={0,0,0,0};
    #pragma unroll 2
    for (int hh = 0; hh < 256; hh++) {
        float x0 = xp[hh*256], x1 = xp[hh*256 + HW], x2 = xp[hh*256 + 2*HW];
        float4 p0 = *(const float4*)&ph[hh][0];
        float4 p1 = *(const float4*)&ph[hh][4];
        float4 wes[4] = {we0, we1, we2c, we3};
        #pragma unroll
        for (int q = 0; q < 4; q++) {
            float pre = fmaf(wes[q].x, x0, fmaf(wes[q].y, x1, fmaf(wes[q].z, x2, wes[q].w)));
            float v = fmaf(-4.f, tanh_rcp(pre), 2.f);
            A0[q] += v;
            AR1[q] = fmaf(v, p0.x, AR1[q]);  B1[q] = fmaf(v, p0.y, B1[q]);
            AR2[q] = fmaf(v, p0.z, AR2[q]);  B2[q] = fmaf(v, p0.w, B2[q]);
            AR3[q] = fmaf(v, p1.x, AR3[q]);  B3[q] = fmaf(v, p1.y, B3[q]);
            AR4[q] = fmaf(v, p1.z, AR4[q]);  B4[q] = fmaf(v, p1.w, B4[q]);
        }
    }

    float cyk[4] = {1.f, c1, c2, c3};
    float syk[4] = {0.f, s1, s2, s3};
    int lane = w & 31, wid = w >> 5;

    #pragma unroll
    for (int ch = 0; ch < 4; ch++) {
        float crr[8] = {A0[ch],  AR1[ch], AR2[ch], AR3[ch], AR4[ch], AR3[ch], AR2[ch], AR1[ch]};
        float cii[8] = {0.f, -B1[ch], -B2[ch], -B3[ch],  B4[ch],  B3[ch],  B2[ch],  B1[ch]};
        #pragma unroll
        for (int kxi = 0; kxi < 8; kxi++) {
            #pragma unroll
            for (int ky = 0; ky < 4; ky++) {
                float re = crr[kxi]*cyk[ky] + cii[kxi]*syk[ky];
                float im = cii[kxi]*cyk[ky] - crr[kxi]*syk[ky];
                #pragma unroll
                for (int o = 16; o > 0; o >>= 1) {
                    re += __shfl_xor_sync(0xffffffffu, re, o);
                    im += __shfl_xor_sync(0xffffffffu, im, o);
                }
                if (lane == 0) {
                    red[wid][(kxi*4+ky)*2    ] = re;
                    red[wid][(kxi*4+ky)*2 + 1] = im;
                }
            }
        }
        __syncthreads();
        if (w < 64) {
            float s = 0.f;
            #pragma unroll
            for (int q = 0; q < 8; q++) s += red[q][w];
            g_v[(b*CH + c0 + ch)*64 + w] = s;
        }
        __syncthreads();
    }
}

// ---------------------------------------------------------------------------
// K3: ALL 6 mode-space iterations fused. Unchanged.
// ---------------------------------------------------------------------------
__global__ void __launch_bounds__(128) k_mix6()
{
    extern __shared__ float smw[];
    float* swr = smw;
    float* swi = smw + 8192;
    __shared__ float vr[2][64], vi[2][64], gr[2][64], gi[2][64], fr[2][64], fi[2][64];

    int g = blockIdx.x, b = blockIdx.y, tid = threadIdx.x;
    int s0, s1 = -1, tmode;
    if (g < 24)      { int kxi=g/3, ky=g%3+1; s0=kxi*4+ky; tmode=0; }
    else if (g==24)  { s0=0;           tmode=1; }
    else if (g==25)  { s0=16;          tmode=2; }
    else if (g==26)  { s0=4;  s1=28;   tmode=3; }
    else if (g==27)  { s0=8;  s1=24;   tmode=3; }
    else             { s0=12; s1=20;   tmode=3; }
    int nsl = (s1 >= 0) ? 2 : 1;

    for (int q = 0; q < nsl; q++) {
        int s = q ? s1 : s0;
        for (int idx = tid; idx < 4096; idx += 128) {
            swr[q*4096 + idx] = g_wre[s*4096 + idx];
            swi[q*4096 + idx] = g_wim[s*4096 + idx];
        }
    }
    int sl = tid >> 6, o = tid & 63;
    if (sl < nsl) {
        int s = sl ? s1 : s0;
        int base = (b*64 + o)*64 + s*2;
        vr[sl][o] = g_v[base]; vi[sl][o] = g_v[base+1];
    }
    __syncthreads();

    for (int it = 0; it < 6; it++) {
        if (sl < nsl) {
            float tr = 0.f, ti = 0.f;
            if (it > 0) {
                float grv = gr[sl][o], giv = gi[sl][o];
                if      (tmode == 0) { tr = grv;       ti = giv; }
                else if (tmode == 1) { tr = grv;       ti = 0.f; }
                else if (tmode == 2) { tr = 0.5f*grv;  ti = 0.5f*giv; }
                else { tr = 0.5f*(grv + gr[1-sl][o]);  ti = 0.5f*(giv - gi[1-sl][o]); }
            }
            fr[sl][o] = vr[sl][o] + tr;
            fi[sl][o] = vi[sl][o] + ti;
        }
        __syncthreads();
        float accr = 0.f, acci = 0.f;
        if (sl < nsl) {
            const float* wrp = swr + sl*4096;
            const float* wip = swi + sl*4096;
            #pragma unroll 8
            for (int i = 0; i < 64; i++) {
                float w_r = wrp[i*64 + o], w_i = wip[i*64 + o];
                float f_r = fr[sl][i],     f_i = fi[sl][i];
                accr = fmaf(f_r, w_r, accr); accr = fmaf(-f_i, w_i, accr);
                acci = fmaf(f_r, w_i, acci); acci = fmaf( f_i, w_r, acci);
            }
        }
        __syncthreads();
        if (sl < nsl) {
            float g0r = it ? gr[sl][o] : 0.f;
            float g0i = it ? gi[sl][o] : 0.f;
            gr[sl][o] = g0r + accr;
            gi[sl][o] = g0i + acci;
        }
        __syncthreads();
    }

    if (sl < nsl) {
        int s = sl ? s1 : s0;
        int base = (b*64 + o)*64 + s*2;
        g_gA[base]   = gr[sl][o];
        g_gA[base+1] = gi[sl][o];
    }
}

// ---------------------------------------------------------------------------
// K5: recon-once epilogue — R13 version VERBATIM (144 us measured best).
// ---------------------------------------------------------------------------
#define HVS_SMEM (64*128*8)

__global__ void __launch_bounds__(256, 2) k_final(
    const float* __restrict__ x,
    const float* __restrict__ ew, const float* __restrict__ eb,
    const float* __restrict__ d1w, const float* __restrict__ d1b,
    const float* __restrict__ d2w, const float* __restrict__ d2b,
    float* __restrict__ out)
{
    extern __shared__ u64 hvs[];     // [64][128] u64 = 64 KB dynamic
    __shared__ u64 zp[64*8];
    __shared__ float gm[4096];
    __shared__ float4 wenc[64];
    __shared__ u64 wp[64*32];
    __shared__ u64 b1p[32], w2p[32];
    __shared__ float pA[2][128], pB[2][128];

    int t = threadIdx.x, b = blockIdx.y;
    int hpair = blockIdx.x & 127, wtile = blockIdx.x >> 7;
    int wv = t & 127, oh = t >> 7;
    int h0 = hpair*2, h1 = h0 + 1;
    int w = wtile*128 + wv;

    for (int idx = t; idx < 2048; idx += 256) {
        int c = idx & 63, op = idx >> 6;
        wp[c*32 + op] = pk2(d1w[(2*op)*64 + c], d1w[(2*op+1)*64 + c]);
    }
    if (t < 32) {
        b1p[t] = pk2(d1b[2*t], d1b[2*t+1]);
        w2p[t] = pk2(d2w[2*t], d2w[2*t+1]);
    }
    if (t < 64) {
        const float K = 2.8853900817779268f;
        wenc[t] = make_float4(K*ew[3*t], K*ew[3*t+1], K*ew[3*t+2], K*eb[t]);
    }
    {
        const float4* gsrc = (const float4*)(g_gA + b*4096);
        float4* gdst = (float4*)gm;
        #pragma unroll
        for (int i = 0; i < 4; i++) gdst[t + i*256] = gsrc[t + i*256];
    }
    __syncthreads();

    {
        int c = t >> 2, ky = t & 3;
        float zrA = 0.f, ziA = 0.f, zrB = 0.f, ziB = 0.f;
        float aA = 6.28318530717958647692f * (1.0f/256.0f) * (float)h0;
        float c1A, s1A; sincosf(aA, &s1A, &c1A);
        float c2A = c1A*c1A - s1A*s1A,  s2A = 2.f*s1A*c1A;
        float c3A = c2A*c1A - s2A*s1A,  s3A = s2A*c1A + c2A*s1A;
        float c4A = c2A*c2A - s2A*s2A,  s4A = 2.f*s2A*c2A;
        float pcA[8] = {1.f, c1A, c2A, c3A,  c4A,  c3A,  c2A,  c1A};
        float psA[8] = {0.f, s1A, s2A, s3A, -s4A, -s3A, -s2A, -s1A};
        float aB = 6.28318530717958647692f * (1.0f/256.0f) * (float)h1;
        float c1B, s1B; sincosf(aB, &s1B, &c1B);
        float c2B = c1B*c1B - s1B*s1B,  s2B = 2.f*s1B*c1B;
        float c3B = c2B*c1B - s2B*s1B,  s3B = s2B*c1B + c2B*s1B;
        float c4B = c2B*c2B - s2B*s2B,  s4B = 2.f*s2B*c2B;
        float pcB[8] = {1.f, c1B, c2B, c3B,  c4B,  c3B,  c2B,  c1B};
        float psB[8] = {0.f, s1B, s2B, s3B, -s4B, -s3B, -s2B, -s1B};
        #pragma unroll
        for (int kxi = 0; kxi < 8; kxi++) {
            float grv = gm[c*64 + kxi*8 + ky*2];
            float giv = gm[c*64 + kxi*8 + ky*2 + 1];
            zrA += grv*pcA[kxi] - giv*psA[kxi];
            ziA += grv*psA[kxi] + giv*pcA[kxi];
            zrB += grv*pcB[kxi] - giv*psB[kxi];
            ziB += grv*psB[kxi] + giv*pcB[kxi];
        }
        if (ky == 0) {
            zp[c*8]     = pk2(zrA*(1.f/131072.f) + 2.f, zrB*(1.f/131072.f) + 2.f);
            zp[c*8 + 7] = 0ull;
        } else {
            zp[c*8 + ky*2 - 1] = pk2( zrA*(1.f/65536.f),  zrB*(1.f/65536.f));
            zp[c*8 + ky*2]     = pk2(-ziA*(1.f/65536.f), -ziB*(1.f/65536.f));
        }
    }
    __syncthreads();

    float a = 6.28318530717958647692f * (1.0f/256.0f) * (float)w;
    float cy1, sy1; sincosf(a, &sy1, &cy1);
    float cy2 = cy1*cy1 - sy1*sy1, sy2 = 2.f*sy1*cy1;
    float cy3 = cy2*cy1 - sy2*sy1, sy3 = sy2*cy1 + cy2*sy1;
    u64 C1 = splat2(cy1), S1 = splat2(sy1);
    u64 C2 = splat2(cy2), S2 = splat2(sy2);
    u64 C3 = splat2(cy3), S3 = splat2(sy3);
    u64 M4 = splat2(-4.f);

    const float* xpA = x + (b*3)*HW + h0*WW + w;
    float x0A = xpA[0],    x0B = xpA[WW];
    float x1A = xpA[HW],   x1B = xpA[HW+WW];
    float x2A = xpA[2*HW], x2B = xpA[2*HW+WW];

    // --- Phase 1: recon HALF the c range into hvs ---
    {
        int cbeg = oh * 32;
        const ulonglong2* zrow2 = (const ulonglong2*)zp;
        #pragma unroll 8
        for (int c = cbeg; c < cbeg + 32; c++) {
            float4 we = wenc[c];
            float preA = fmaf(we.x, x0A, fmaf(we.y, x1A, fmaf(we.z, x2A, we.w)));
            float preB = fmaf(we.x, x0B, fmaf(we.y, x1B, fmaf(we.z, x2B, we.w)));
            float eA, rA, eB, rB;
            asm("ex2.approx.f32 %0, %1;" : "=f"(eA) : "f"(preA));
            asm("ex2.approx.f32 %0, %1;" : "=f"(eB) : "f"(preB));
            asm("rcp.approx.f32 %0, %1;" : "=f"(rA) : "f"(eA + 1.0f));
            asm("rcp.approx.f32 %0, %1;" : "=f"(rB) : "f"(eB + 1.0f));
            ulonglong2 z01 = zrow2[c*4], z23 = zrow2[c*4+1], z45 = zrow2[c*4+2], z67 = zrow2[c*4+3];
            u64 hv2 = f2fma(pk2(rA, rB), M4, z01.x);
            hv2 = f2fma(z01.y, C1, hv2);
            hv2 = f2fma(z23.x, S1, hv2);
            hv2 = f2fma(z23.y, C2, hv2);
            hv2 = f2fma(z45.x, S2, hv2);
            hv2 = f2fma(z45.y, C3, hv2);
            hv2 = f2fma(z67.x, S3, hv2);
            hvs[c*128 + wv] = hv2;
        }
    }
    __syncthreads();

    // --- Phase 2: GEMV over all 64 c from hvs ---
    u64 accA[16], accB[16];
    #pragma unroll
    for (int k = 0; k < 16; k++) { u64 bb = b1p[oh*16 + k]; accA[k] = bb; accB[k] = bb; }

    const ulonglong2* wrow = (const ulonglong2*)&wp[oh*16];
    #pragma unroll 8
    for (int c = 0; c < 64; c++) {
        u64 hv2 = hvs[c*128 + wv];
        float2 hv = upk2(hv2);
        u64 hsA = splat2(hv.x), hsB = splat2(hv.y);
        const ulonglong2* wr = wrow + c*16;
        #pragma unroll
        for (int k2 = 0; k2 < 8; k2++) {
            ulonglong2 wv2 = wr[k2];
            accA[k2*2]   = f2fma(hsA, wv2.x, accA[k2*2]);
            accA[k2*2+1] = f2fma(hsA, wv2.y, accA[k2*2+1]);
            accB[k2*2]   = f2fma(hsB, wv2.x, accB[k2*2]);
            accB[k2*2+1] = f2fma(hsB, wv2.y, accB[k2*2+1]);
        }
    }

    u64 oaccA = 0ull, oaccB = 0ull;
    #pragma unroll
    for (int k = 0; k < 16; k++) {
        u64 w2v = w2p[oh*16 + k];
        float2 vA = upk2(accA[k]);
        float2 vB = upk2(accB[k]);
        oaccA = f2fma(pk2(fast_tanh(vA.x), fast_tanh(vA.y)), w2v, oaccA);
        oaccB = f2fma(pk2(fast_tanh(vB.x), fast_tanh(vB.y)), w2v, oaccB);
    }
    float2 oA = upk2(oaccA), oB = upk2(oaccB);
    pA[oh][wv] = oA.x + oA.y;
    pB[oh][wv] = oB.x + oB.y;
    __syncthreads();

    float b2v = d2b[0];
    if (oh == 0) {
        out[b*HW + h0*WW + w] = pA[0][wv] + pA[1][wv] + b2v;
    } else {
        out[b*HW + h1*WW + w] = pB[0][wv] + pB[1][wv] + b2v;
    }
}

extern "C" void kernel_launch(void* const* d_in, const int* in_sizes, int n_in,
                              void* d_out, int out_size)
{
    const float* x   = (const float*)d_in[0];
    const float* ew  = (const float*)d_in[1];
    const float* eb  = (const float*)d_in[2];
    const float* d1w = (const float*)d_in[3];
    const float* d1b = (const float*)d_in[4];
    const float* d2w = (const float*)d_in[5];
    const float* d2b = (const float*)d_in[6];
    const float* w1r = (const float*)d_in[7];
    const float* w1i = (const float*)d_in[8];
    const float* w2r = (const float*)d_in[9];
    const float* w2i = (const float*)d_in[10];
    float* out = (float*)d_out;

    cudaFuncSetAttribute(k_mix6, cudaFuncAttributeMaxDynamicSharedMemorySize, 65536);
    cudaFuncSetAttribute(k_final, cudaFuncAttributeMaxDynamicSharedMemorySize, HVS_SMEM);

    k_repack<<<32, 256>>>(w1r, w1i, w2r, w2i);
    k_project<<<dim3(16, 8), 256>>>(x, ew, eb);
    k_mix6<<<dim3(29, 8), 128, 65536>>>();
    k_final<<<dim3(256, 8), 256, HVS_SMEM>>>(x, ew, eb, d1w, d1b, d2w, d2b, out);
}

// round 16
// speedup vs baseline: 1.1964x; 1.1229x over previous
#include <cuda_runtime.h>
#include <math.h>
#include <stdint.h>

#define BB 8
#define CH 64
#define HH 256
#define WW 256
#define HW 65536

typedef unsigned long long u64;

__device__ __forceinline__ u64 pk2(float lo, float hi){ u64 r; asm("mov.b64 %0,{%1,%2};" : "=l"(r) : "f"(lo), "f"(hi)); return r; }
__device__ __forceinline__ u64 splat2(float v){ u64 r; asm("mov.b64 %0,{%1,%1};" : "=l"(r) : "f"(v)); return r; }
__device__ __forceinline__ float2 upk2(u64 a){ float2 f; asm("mov.b64 {%0,%1},%2;" : "=f"(f.x), "=f"(f.y) : "l"(a)); return f; }
__device__ __forceinline__ u64 f2fma(u64 a, u64 b, u64 c){ u64 d; asm("fma.rn.f32x2 %0,%1,%2,%3;" : "=l"(d) : "l"(a), "l"(b), "l"(c)); return d; }

__device__ __forceinline__ float fast_tanh(float x){
    float e, r;
    asm("ex2.approx.f32 %0, %1;" : "=f"(e) : "f"(x * 2.8853900817779268f));
    asm("rcp.approx.f32 %0, %1;" : "=f"(r) : "f"(e + 1.0f));
    return fmaf(-2.0f, r, 1.0f);
}
__device__ __forceinline__ float tanh_rcp(float x){
    float e, r;
    asm("ex2.approx.f32 %0, %1;" : "=f"(e) : "f"(x * 2.8853900817779268f));
    asm("rcp.approx.f32 %0, %1;" : "=f"(r) : "f"(e + 1.0f));
    return r;
}

// Scratch
__device__ float g_vp[2*BB*CH*64];   // partial modes: [half][b][c][64]
__device__ float g_gA[BB*CH*64];
__device__ float g_wre[32*4096];
__device__ float g_wim[32*4096];

// ---------------------------------------------------------------------------
// K0: repack spectral weights. Unchanged.
// ---------------------------------------------------------------------------
__global__ void k_repack(const float* __restrict__ w1r, const float* __restrict__ w1i,
                         const float* __restrict__ w2r, const float* __restrict__ w2i)
{
    int s = blockIdx.x;
    int kxi = s >> 2, ky = s & 3;
    const float* srcr = (kxi < 4) ? w1r : w2r;
    const float* srci = (kxi < 4) ? w1i : w2i;
    int kk = (kxi & 3) * 4 + ky;
    for (int idx = threadIdx.x; idx < 4096; idx += blockDim.x) {
        g_wre[s*4096 + idx] = srcr[idx*16 + kk];
        g_wim[s*4096 + idx] = srci[idx*16 + kk];
    }
}

// ---------------------------------------------------------------------------
// K2: projection, 2 channels per block, SPLIT over h halves (blockIdx.z).
// Each block integrates 128 rows; partial v written to g_vp[half].
// grid = (32, 8, 2), block = 256.
// ---------------------------------------------------------------------------
__global__ void __launch_bounds__(256) k_project(
    const float* __restrict__ x,
    const float* __restrict__ ew,
    const float* __restrict__ eb)
{
    __shared__ float ph[128][8];
    __shared__ float red[8][64];
    __shared__ float4 wenc2[2];
    int w = threadIdx.x, cg = blockIdx.x, b = blockIdx.y, hb = blockIdx.z;
    int c0 = cg * 2;
    if (w < 2) wenc2[w] = make_float4(ew[3*(c0+w)], ew[3*(c0+w)+1], ew[3*(c0+w)+2], eb[c0+w]);

    // row phases for this half (threads 0..127 fill)
    if (w < 128) {
        float ar = 6.28318530717958647692f * (1.0f/256.0f) * (float)(hb*128 + w);
        float rc1, rs1; sincosf(ar, &rs1, &rc1);
        float rc2 = rc1*rc1 - rs1*rs1,  rs2 = 2.f*rs1*rc1;
        float rc3 = rc2*rc1 - rs2*rs1,  rs3 = rs2*rc1 + rc2*rs1;
        float rc4 = rc2*rc2 - rs2*rs2,  rs4 = 2.f*rs2*rc2;
        ph[w][0]=rc1; ph[w][1]=rs1; ph[w][2]=rc2; ph[w][3]=rs2;
        ph[w][4]=rc3; ph[w][5]=rs3; ph[w][6]=rc4; ph[w][7]=rs4;
    }
    // column phases for this thread
    float a = 6.28318530717958647692f * (1.0f/256.0f) * (float)w;
    float c1, s1; sincosf(a, &s1, &c1);
    float c2 = c1*c1 - s1*s1,  s2 = 2.f*s1*c1;
    float c3 = c2*c1 - s2*s1,  s3 = s2*c1 + c2*s1;
    __syncthreads();

    float4 weA = wenc2[0], weB = wenc2[1];
    const float* xp = x + (b*3)*HW + hb*128*256 + w;
    float A0[2]={0,0}, AR1[2]={0,0}, B1[2]={0,0}, AR2[2]={0,0}, B2[2]={0,0},
          AR3[2]={0,0}, B3[2]={0,0}, AR4[2]={0,0}, B4[2]={0,0};
    #pragma unroll 2
    for (int hh = 0; hh < 128; hh++) {
        float x0 = xp[hh*256], x1 = xp[hh*256 + HW], x2 = xp[hh*256 + 2*HW];
        float4 p0 = *(const float4*)&ph[hh][0];
        float4 p1 = *(const float4*)&ph[hh][4];
        {
            float pre = fmaf(weA.x, x0, fmaf(weA.y, x1, fmaf(weA.z, x2, weA.w)));
            float v = fmaf(-4.f, tanh_rcp(pre), 2.f);
            A0[0] += v;
            AR1[0] = fmaf(v, p0.x, AR1[0]);  B1[0] = fmaf(v, p0.y, B1[0]);
            AR2[0] = fmaf(v, p0.z, AR2[0]);  B2[0] = fmaf(v, p0.w, B2[0]);
            AR3[0] = fmaf(v, p1.x, AR3[0]);  B3[0] = fmaf(v, p1.y, B3[0]);
            AR4[0] = fmaf(v, p1.z, AR4[0]);  B4[0] = fmaf(v, p1.w, B4[0]);
        }
        {
            float pre = fmaf(weB.x, x0, fmaf(weB.y, x1, fmaf(weB.z, x2, weB.w)));
            float v = fmaf(-4.f, tanh_rcp(pre), 2.f);
            A0[1] += v;
            AR1[1] = fmaf(v, p0.x, AR1[1]);  B1[1] = fmaf(v, p0.y, B1[1]);
            AR2[1] = fmaf(v, p0.z, AR2[1]);  B2[1] = fmaf(v, p0.w, B2[1]);
            AR3[1] = fmaf(v, p1.x, AR3[1]);  B3[1] = fmaf(v, p1.y, B3[1]);
            AR4[1] = fmaf(v, p1.z, AR4[1]);  B4[1] = fmaf(v, p1.w, B4[1]);
        }
    }

    float cyk[4] = {1.f, c1, c2, c3};
    float syk[4] = {0.f, s1, s2, s3};
    int lane = w & 31, wid = w >> 5;

    #pragma unroll
    for (int ch = 0; ch < 2; ch++) {
        float crr[8] = {A0[ch],  AR1[ch], AR2[ch], AR3[ch], AR4[ch], AR3[ch], AR2[ch], AR1[ch]};
        float cii[8] = {0.f, -B1[ch], -B2[ch], -B3[ch],  B4[ch],  B3[ch],  B2[ch],  B1[ch]};
        #pragma unroll
        for (int kxi = 0; kxi < 8; kxi++) {
            #pragma unroll
            for (int ky = 0; ky < 4; ky++) {
                float re = crr[kxi]*cyk[ky] + cii[kxi]*syk[ky];
                float im = cii[kxi]*cyk[ky] - crr[kxi]*syk[ky];
                #pragma unroll
                for (int o = 16; o > 0; o >>= 1) {
                    re += __shfl_xor_sync(0xffffffffu, re, o);
                    im += __shfl_xor_sync(0xffffffffu, im, o);
                }
                if (lane == 0) {
                    red[wid][(kxi*4+ky)*2    ] = re;
                    red[wid][(kxi*4+ky)*2 + 1] = im;
                }
            }
        }
        __syncthreads();
        if (w < 64) {
            float s = 0.f;
            #pragma unroll
            for (int q = 0; q < 8; q++) s += red[q][w];
            g_vp[((hb*BB + b)*CH + c0 + ch)*64 + w] = s;
        }
        __syncthreads();
    }
}

// ---------------------------------------------------------------------------
// K3: ALL 6 mode-space iterations fused; v loaded as sum of two h-half
// partials. Otherwise unchanged.
// ---------------------------------------------------------------------------
__global__ void __launch_bounds__(128) k_mix6()
{
    extern __shared__ float smw[];
    float* swr = smw;
    float* swi = smw + 8192;
    __shared__ float vr[2][64], vi[2][64], gr[2][64], gi[2][64], fr[2][64], fi[2][64];

    int g = blockIdx.x, b = blockIdx.y, tid = threadIdx.x;
    int s0, s1 = -1, tmode;
    if (g < 24)      { int kxi=g/3, ky=g%3+1; s0=kxi*4+ky; tmode=0; }
    else if (g==24)  { s0=0;           tmode=1; }
    else if (g==25)  { s0=16;          tmode=2; }
    else if (g==26)  { s0=4;  s1=28;   tmode=3; }
    else if (g==27)  { s0=8;  s1=24;   tmode=3; }
    else             { s0=12; s1=20;   tmode=3; }
    int nsl = (s1 >= 0) ? 2 : 1;

    for (int q = 0; q < nsl; q++) {
        int s = q ? s1 : s0;
        for (int idx = tid; idx < 4096; idx += 128) {
            swr[q*4096 + idx] = g_wre[s*4096 + idx];
            swi[q*4096 + idx] = g_wim[s*4096 + idx];
        }
    }
    int sl = tid >> 6, o = tid & 63;
    if (sl < nsl) {
        int s = sl ? s1 : s0;
        int base = (b*CH + o)*64 + s*2;
        vr[sl][o] = g_vp[base] + g_vp[base + BB*CH*64];
        vi[sl][o] = g_vp[base+1] + g_vp[base+1 + BB*CH*64];
    }
    __syncthreads();

    for (int it = 0; it < 6; it++) {
        if (sl < nsl) {
            float tr = 0.f, ti = 0.f;
            if (it > 0) {
                float grv = gr[sl][o], giv = gi[sl][o];
                if      (tmode == 0) { tr = grv;       ti = giv; }
                else if (tmode == 1) { tr = grv;       ti = 0.f; }
                else if (tmode == 2) { tr = 0.5f*grv;  ti = 0.5f*giv; }
                else { tr = 0.5f*(grv + gr[1-sl][o]);  ti = 0.5f*(giv - gi[1-sl][o]); }
            }
            fr[sl][o] = vr[sl][o] + tr;
            fi[sl][o] = vi[sl][o] + ti;
        }
        __syncthreads();
        float accr = 0.f, acci = 0.f;
        if (sl < nsl) {
            const float* wrp = swr + sl*4096;
            const float* wip = swi + sl*4096;
            #pragma unroll 8
            for (int i = 0; i < 64; i++) {
                float w_r = wrp[i*64 + o], w_i = wip[i*64 + o];
                float f_r = fr[sl][i],     f_i = fi[sl][i];
                accr = fmaf(f_r, w_r, accr); accr = fmaf(-f_i, w_i, accr);
                acci = fmaf(f_r, w_i, acci); acci = fmaf( f_i, w_r, acci);
            }
        }
        __syncthreads();
        if (sl < nsl) {
            float g0r = it ? gr[sl][o] : 0.f;
            float g0i = it ? gi[sl][o] : 0.f;
            gr[sl][o] = g0r + accr;
            gi[sl][o] = g0i + acci;
        }
        __syncthreads();
    }

    if (sl < nsl) {
        int s = sl ? s1 : s0;
        int base = (b*CH + o)*64 + s*2;
        g_gA[base]   = gr[sl][o];
        g_gA[base+1] = gi[sl][o];
    }
}

// ---------------------------------------------------------------------------
// K5: recon-once epilogue — R13 version VERBATIM (144 us measured best).
// ---------------------------------------------------------------------------
#define HVS_SMEM (64*128*8)

__global__ void __launch_bounds__(256, 2) k_final(
    const float* __restrict__ x,
    const float* __restrict__ ew, const float* __restrict__ eb,
    const float* __restrict__ d1w, const float* __restrict__ d1b,
    const float* __restrict__ d2w, const float* __restrict__ d2b,
    float* __restrict__ out)
{
    extern __shared__ u64 hvs[];     // [64][128] u64 = 64 KB dynamic
    __shared__ u64 zp[64*8];
    __shared__ float gm[4096];
    __shared__ float4 wenc[64];
    __shared__ u64 wp[64*32];
    __shared__ u64 b1p[32], w2p[32];
    __shared__ float pA[2][128], pB[2][128];

    int t = threadIdx.x, b = blockIdx.y;
    int hpair = blockIdx.x & 127, wtile = blockIdx.x >> 7;
    int wv = t & 127, oh = t >> 7;
    int h0 = hpair*2, h1 = h0 + 1;
    int w = wtile*128 + wv;

    for (int idx = t; idx < 2048; idx += 256) {
        int c = idx & 63, op = idx >> 6;
        wp[c*32 + op] = pk2(d1w[(2*op)*64 + c], d1w[(2*op+1)*64 + c]);
    }
    if (t < 32) {
        b1p[t] = pk2(d1b[2*t], d1b[2*t+1]);
        w2p[t] = pk2(d2w[2*t], d2w[2*t+1]);
    }
    if (t < 64) {
        const float K = 2.8853900817779268f;
        wenc[t] = make_float4(K*ew[3*t], K*ew[3*t+1], K*ew[3*t+2], K*eb[t]);
    }
    {
        const float4* gsrc = (const float4*)(g_gA + b*4096);
        float4* gdst = (float4*)gm;
        #pragma unroll
        for (int i = 0; i < 4; i++) gdst[t + i*256] = gsrc[t + i*256];
    }
    __syncthreads();

    {
        int c = t >> 2, ky = t & 3;
        float zrA = 0.f, ziA = 0.f, zrB = 0.f, ziB = 0.f;
        float aA = 6.28318530717958647692f * (1.0f/256.0f) * (float)h0;
        float c1A, s1A; sincosf(aA, &s1A, &c1A);
        float c2A = c1A*c1A - s1A*s1A,  s2A = 2.f*s1A*c1A;
        float c3A = c2A*c1A - s2A*s1A,  s3A = s2A*c1A + c2A*s1A;
        float c4A = c2A*c2A - s2A*s2A,  s4A = 2.f*s2A*c2A;
        float pcA[8] = {1.f, c1A, c2A, c3A,  c4A,  c3A,  c2A,  c1A};
        float psA[8] = {0.f, s1A, s2A, s3A, -s4A, -s3A, -s2A, -s1A};
        float aB = 6.28318530717958647692f * (1.0f/256.0f) * (float)h1;
        float c1B, s1B; sincosf(aB, &s1B, &c1B);
        float c2B = c1B*c1B - s1B*s1B,  s2B = 2.f*s1B*c1B;
        float c3B = c2B*c1B - s2B*s1B,  s3B = s2B*c1B + c2B*s1B;
        float c4B = c2B*c2B - s2B*s2B,  s4B = 2.f*s2B*c2B;
        float pcB[8] = {1.f, c1B, c2B, c3B,  c4B,  c3B,  c2B,  c1B};
        float psB[8] = {0.f, s1B, s2B, s3B, -s4B, -s3B, -s2B, -s1B};
        #pragma unroll
        for (int kxi = 0; kxi < 8; kxi++) {
            float grv = gm[c*64 + kxi*8 + ky*2];
            float giv = gm[c*64 + kxi*8 + ky*2 + 1];
            zrA += grv*pcA[kxi] - giv*psA[kxi];
            ziA += grv*psA[kxi] + giv*pcA[kxi];
            zrB += grv*pcB[kxi] - giv*psB[kxi];
            ziB += grv*psB[kxi] + giv*pcB[kxi];
        }
        if (ky == 0) {
            zp[c*8]     = pk2(zrA*(1.f/131072.f) + 2.f, zrB*(1.f/131072.f) + 2.f);
            zp[c*8 + 7] = 0ull;
        } else {
            zp[c*8 + ky*2 - 1] = pk2( zrA*(1.f/65536.f),  zrB*(1.f/65536.f));
            zp[c*8 + ky*2]     = pk2(-ziA*(1.f/65536.f), -ziB*(1.f/65536.f));
        }
    }
    __syncthreads();

    float a = 6.28318530717958647692f * (1.0f/256.0f) * (float)w;
    float cy1, sy1; sincosf(a, &sy1, &cy1);
    float cy2 = cy1*cy1 - sy1*sy1, sy2 = 2.f*sy1*cy1;
    float cy3 = cy2*cy1 - sy2*sy1, sy3 = sy2*cy1 + cy2*sy1;
    u64 C1 = splat2(cy1), S1 = splat2(sy1);
    u64 C2 = splat2(cy2), S2 = splat2(sy2);
    u64 C3 = splat2(cy3), S3 = splat2(sy3);
    u64 M4 = splat2(-4.f);

    const float* xpA = x + (b*3)*HW + h0*WW + w;
    float x0A = xpA[0],    x0B = xpA[WW];
    float x1A = xpA[HW],   x1B = xpA[HW+WW];
    float x2A = xpA[2*HW], x2B = xpA[2*HW+WW];

    // --- Phase 1: recon HALF the c range into hvs ---
    {
        int cbeg = oh * 32;
        const ulonglong2* zrow2 = (const ulonglong2*)zp;
        #pragma unroll 8
        for (int c = cbeg; c < cbeg + 32; c++) {
            float4 we = wenc[c];
            float preA = fmaf(we.x, x0A, fmaf(we.y, x1A, fmaf(we.z, x2A, we.w)));
            float preB = fmaf(we.x, x0B, fmaf(we.y, x1B, fmaf(we.z, x2B, we.w)));
            float eA, rA, eB, rB;
            asm("ex2.approx.f32 %0, %1;" : "=f"(eA) : "f"(preA));
            asm("ex2.approx.f32 %0, %1;" : "=f"(eB) : "f"(preB));
            asm("rcp.approx.f32 %0, %1;" : "=f"(rA) : "f"(eA + 1.0f));
            asm("rcp.approx.f32 %0, %1;" : "=f"(rB) : "f"(eB + 1.0f));
            ulonglong2 z01 = zrow2[c*4], z23 = zrow2[c*4+1], z45 = zrow2[c*4+2], z67 = zrow2[c*4+3];
            u64 hv2 = f2fma(pk2(rA, rB), M4, z01.x);
            hv2 = f2fma(z01.y, C1, hv2);
            hv2 = f2fma(z23.x, S1, hv2);
            hv2 = f2fma(z23.y, C2, hv2);
            hv2 = f2fma(z45.x, S2, hv2);
            hv2 = f2fma(z45.y, C3, hv2);
            hv2 = f2fma(z67.x, S3, hv2);
            hvs[c*128 + wv] = hv2;
        }
    }
    __syncthreads();

    // --- Phase 2: GEMV over all 64 c from hvs ---
    u64 accA[16], accB[16];
    #pragma unroll
    for (int k = 0; k < 16; k++) { u64 bb = b1p[oh*16 + k]; accA[k] = bb; accB[k] = bb; }

    const ulonglong2* wrow = (const ulonglong2*)&wp[oh*16];
    #pragma unroll 8
    for (int c = 0; c < 64; c++) {
        u64 hv2 = hvs[c*128 + wv];
        float2 hv = upk2(hv2);
        u64 hsA = splat2(hv.x), hsB = splat2(hv.y);
        const ulonglong2* wr = wrow + c*16;
        #pragma unroll
        for (int k2 = 0; k2 < 8; k2++) {
            ulonglong2 wv2 = wr[k2];
            accA[k2*2]   = f2fma(hsA, wv2.x, accA[k2*2]);
            accA[k2*2+1] = f2fma(hsA, wv2.y, accA[k2*2+1]);
            accB[k2*2]   = f2fma(hsB, wv2.x, accB[k2*2]);
            accB[k2*2+1] = f2fma(hsB, wv2.y, accB[k2*2+1]);
        }
    }

    u64 oaccA = 0ull, oaccB = 0ull;
    #pragma unroll
    for (int k = 0; k < 16; k++) {
        u64 w2v = w2p[oh*16 + k];
        float2 vA = upk2(accA[k]);
        float2 vB = upk2(accB[k]);
        oaccA = f2fma(pk2(fast_tanh(vA.x), fast_tanh(vA.y)), w2v, oaccA);
        oaccB = f2fma(pk2(fast_tanh(vB.x), fast_tanh(vB.y)), w2v, oaccB);
    }
    float2 oA = upk2(oaccA), oB = upk2(oaccB);
    pA[oh][wv] = oA.x + oA.y;
    pB[oh][wv] = oB.x + oB.y;
    __syncthreads();

    float b2v = d2b[0];
    if (oh == 0) {
        out[b*HW + h0*WW + w] = pA[0][wv] + pA[1][wv] + b2v;
    } else {
        out[b*HW + h1*WW + w] = pB[0][wv] + pB[1][wv] + b2v;
    }
}

extern "C" void kernel_launch(void* const* d_in, const int* in_sizes, int n_in,
                              void* d_out, int out_size)
{
    const float* x   = (const float*)d_in[0];
    const float* ew  = (const float*)d_in[1];
    const float* eb  = (const float*)d_in[2];
    const float* d1w = (const float*)d_in[3];
    const float* d1b = (const float*)d_in[4];
    const float* d2w = (const float*)d_in[5];
    const float* d2b = (const float*)d_in[6];
    const float* w1r = (const float*)d_in[7];
    const float* w1i = (const float*)d_in[8];
    const float* w2r = (const float*)d_in[9];
    const float* w2i = (const float*)d_in[10];
    float* out = (float*)d_out;

    cudaFuncSetAttribute(k_mix6, cudaFuncAttributeMaxDynamicSharedMemorySize, 65536);
    cudaFuncSetAttribute(k_final, cudaFuncAttributeMaxDynamicSharedMemorySize, HVS_SMEM);

    k_repack<<<32, 256>>>(w1r, w1i, w2r, w2i);
    k_project<<<dim3(32, 8, 2), 256>>>(x, ew, eb);
    k_mix6<<<dim3(29, 8), 128, 65536>>>();
    k_final<<<dim3(256, 8), 256, HVS_SMEM>>>(x, ew, eb, d1w, d1b, d2w, d2b, out);
}

// round 17
// speedup vs baseline: 1.2062x; 1.0082x over previous
#include <cuda_runtime.h>
#include <math.h>
#include <stdint.h>

#define BB 8
#define CH 64
#define HH 256
#define WW 256
#define HW 65536

typedef unsigned long long u64;

__device__ __forceinline__ u64 pk2(float lo, float hi){ u64 r; asm("mov.b64 %0,{%1,%2};" : "=l"(r) : "f"(lo), "f"(hi)); return r; }
__device__ __forceinline__ u64 splat2(float v){ u64 r; asm("mov.b64 %0,{%1,%1};" : "=l"(r) : "f"(v)); return r; }
__device__ __forceinline__ float2 upk2(u64 a){ float2 f; asm("mov.b64 {%0,%1},%2;" : "=f"(f.x), "=f"(f.y) : "l"(a)); return f; }
__device__ __forceinline__ u64 f2fma(u64 a, u64 b, u64 c){ u64 d; asm("fma.rn.f32x2 %0,%1,%2,%3;" : "=l"(d) : "l"(a), "l"(b), "l"(c)); return d; }

__device__ __forceinline__ float fast_tanh(float x){
    float e, r;
    asm("ex2.approx.f32 %0, %1;" : "=f"(e) : "f"(x * 2.8853900817779268f));
    asm("rcp.approx.f32 %0, %1;" : "=f"(r) : "f"(e + 1.0f));
    return fmaf(-2.0f, r, 1.0f);
}
__device__ __forceinline__ float tanh_rcp(float x){
    float e, r;
    asm("ex2.approx.f32 %0, %1;" : "=f"(e) : "f"(x * 2.8853900817779268f));
    asm("rcp.approx.f32 %0, %1;" : "=f"(r) : "f"(e + 1.0f));
    return r;
}

// Scratch
__device__ float g_v [BB*CH*64];
__device__ float g_gA[BB*CH*64];
__device__ float g_wre[32*4096];
__device__ float g_wim[32*4096];

// ---------------------------------------------------------------------------
// K0: repack spectral weights. Unchanged.
// ---------------------------------------------------------------------------
__global__ void k_repack(const float* __restrict__ w1r, const float* __restrict__ w1i,
                         const float* __restrict__ w2r, const float* __restrict__ w2i)
{
    int s = blockIdx.x;
    int kxi = s >> 2, ky = s & 3;
    const float* srcr = (kxi < 4) ? w1r : w2r;
    const float* srci = (kxi < 4) ? w1i : w2i;
    int kk = (kxi & 3) * 4 + ky;
    for (int idx = threadIdx.x; idx < 4096; idx += blockDim.x) {
        g_wre[s*4096 + idx] = srcr[idx*16 + kk];
        g_wim[s*4096 + idx] = srci[idx*16 + kk];
    }
}

// ---------------------------------------------------------------------------
// K2: projection, 2 channels per block, scalar (R13 best). grid=(32,8).
// ---------------------------------------------------------------------------
__global__ void __launch_bounds__(256) k_project(
    const float* __restrict__ x,
    const float* __restrict__ ew,
    const float* __restrict__ eb)
{
    __shared__ float ph[256][8];
    __shared__ float red[8][64];
    __shared__ float4 wenc2[2];
    int w = threadIdx.x, cg = blockIdx.x, b = blockIdx.y;
    int c0 = cg * 2;
    if (w < 2) wenc2[w] = make_float4(ew[3*(c0+w)], ew[3*(c0+w)+1], ew[3*(c0+w)+2], eb[c0+w]);

    float a = 6.28318530717958647692f * (1.0f/256.0f) * (float)w;
    float c1, s1; sincosf(a, &s1, &c1);
    float c2 = c1*c1 - s1*s1,  s2 = 2.f*s1*c1;
    float c3 = c2*c1 - s2*s1,  s3 = s2*c1 + c2*s1;
    float c4 = c2*c2 - s2*s2,  s4 = 2.f*s2*c2;
    ph[w][0]=c1; ph[w][1]=s1; ph[w][2]=c2; ph[w][3]=s2;
    ph[w][4]=c3; ph[w][5]=s3; ph[w][6]=c4; ph[w][7]=s4;
    __syncthreads();

    float4 weA = wenc2[0], weB = wenc2[1];
    const float* xp = x + (b*3)*HW + w;
    float A0[2]={0,0}, AR1[2]={0,0}, B1[2]={0,0}, AR2[2]={0,0}, B2[2]={0,0},
          AR3[2]={0,0}, B3[2]={0,0}, AR4[2]={0,0}, B4[2]={0,0};
    #pragma unroll 2
    for (int hh = 0; hh < 256; hh++) {
        float x0 = xp[hh*256], x1 = xp[hh*256 + HW], x2 = xp[hh*256 + 2*HW];
        float4 p0 = *(const float4*)&ph[hh][0];
        float4 p1 = *(const float4*)&ph[hh][4];
        {
            float pre = fmaf(weA.x, x0, fmaf(weA.y, x1, fmaf(weA.z, x2, weA.w)));
            float v = fmaf(-4.f, tanh_rcp(pre), 2.f);
            A0[0] += v;
            AR1[0] = fmaf(v, p0.x, AR1[0]);  B1[0] = fmaf(v, p0.y, B1[0]);
            AR2[0] = fmaf(v, p0.z, AR2[0]);  B2[0] = fmaf(v, p0.w, B2[0]);
            AR3[0] = fmaf(v, p1.x, AR3[0]);  B3[0] = fmaf(v, p1.y, B3[0]);
            AR4[0] = fmaf(v, p1.z, AR4[0]);  B4[0] = fmaf(v, p1.w, B4[0]);
        }
        {
            float pre = fmaf(weB.x, x0, fmaf(weB.y, x1, fmaf(weB.z, x2, weB.w)));
            float v = fmaf(-4.f, tanh_rcp(pre), 2.f);
            A0[1] += v;
            AR1[1] = fmaf(v, p0.x, AR1[1]);  B1[1] = fmaf(v, p0.y, B1[1]);
            AR2[1] = fmaf(v, p0.z, AR2[1]);  B2[1] = fmaf(v, p0.w, B2[1]);
            AR3[1] = fmaf(v, p1.x, AR3[1]);  B3[1] = fmaf(v, p1.y, B3[1]);
            AR4[1] = fmaf(v, p1.z, AR4[1]);  B4[1] = fmaf(v, p1.w, B4[1]);
        }
    }

    float cyk[4] = {1.f, c1, c2, c3};
    float syk[4] = {0.f, s1, s2, s3};
    int lane = w & 31, wid = w >> 5;

    #pragma unroll
    for (int ch = 0; ch < 2; ch++) {
        float crr[8] = {A0[ch],  AR1[ch], AR2[ch], AR3[ch], AR4[ch], AR3[ch], AR2[ch], AR1[ch]};
        float cii[8] = {0.f, -B1[ch], -B2[ch], -B3[ch],  B4[ch],  B3[ch],  B2[ch],  B1[ch]};
        #pragma unroll
        for (int kxi = 0; kxi < 8; kxi++) {
            #pragma unroll
            for (int ky = 0; ky < 4; ky++) {
                float re = crr[kxi]*cyk[ky] + cii[kxi]*syk[ky];
                float im = cii[kxi]*cyk[ky] - crr[kxi]*syk[ky];
                #pragma unroll
                for (int o = 16; o > 0; o >>= 1) {
                    re += __shfl_xor_sync(0xffffffffu, re, o);
                    im += __shfl_xor_sync(0xffffffffu, im, o);
                }
                if (lane == 0) {
                    red[wid][(kxi*4+ky)*2    ] = re;
                    red[wid][(kxi*4+ky)*2 + 1] = im;
                }
            }
        }
        __syncthreads();
        if (w < 64) {
            float s = 0.f;
            #pragma unroll
            for (int q = 0; q < 8; q++) s += red[q][w];
            g_v[(b*CH + c0 + ch)*64 + w] = s;
        }
        __syncthreads();
    }
}

// ---------------------------------------------------------------------------
// K3: 6 fused mode iterations. nsl==1 groups now use BOTH thread halves
// (i-range split 0-31 / 32-63, partials combined in smem) — halves the
// serial GEMV chain for 24/29 groups. nsl==2 path unchanged.
// ---------------------------------------------------------------------------
__global__ void __launch_bounds__(128) k_mix6()
{
    extern __shared__ float smw[];
    float* swr = smw;
    float* swi = smw + 8192;
    __shared__ float vr[2][64], vi[2][64], gr[2][64], gi[2][64], fr[2][64], fi[2][64];
    __shared__ float pr[64], pi[64];

    int g = blockIdx.x, b = blockIdx.y, tid = threadIdx.x;
    int s0, s1 = -1, tmode;
    if (g < 24)      { int kxi=g/3, ky=g%3+1; s0=kxi*4+ky; tmode=0; }
    else if (g==24)  { s0=0;           tmode=1; }
    else if (g==25)  { s0=16;          tmode=2; }
    else if (g==26)  { s0=4;  s1=28;   tmode=3; }
    else if (g==27)  { s0=8;  s1=24;   tmode=3; }
    else             { s0=12; s1=20;   tmode=3; }
    int nsl = (s1 >= 0) ? 2 : 1;

    for (int q = 0; q < nsl; q++) {
        int s = q ? s1 : s0;
        for (int idx = tid; idx < 4096; idx += 128) {
            swr[q*4096 + idx] = g_wre[s*4096 + idx];
            swi[q*4096 + idx] = g_wim[s*4096 + idx];
        }
    }
    int sl = tid >> 6, o = tid & 63;
    if (sl < nsl) {
        int s = sl ? s1 : s0;
        int base = (b*CH + o)*64 + s*2;
        vr[sl][o] = g_v[base]; vi[sl][o] = g_v[base+1];
    }
    __syncthreads();

    if (nsl == 2) {
        for (int it = 0; it < 6; it++) {
            {
                float tr = 0.f, ti = 0.f;
                if (it > 0) {
                    float grv = gr[sl][o], giv = gi[sl][o];
                    tr = 0.5f*(grv + gr[1-sl][o]);
                    ti = 0.5f*(giv - gi[1-sl][o]);
                }
                fr[sl][o] = vr[sl][o] + tr;
                fi[sl][o] = vi[sl][o] + ti;
            }
            __syncthreads();
            float accr = 0.f, acci = 0.f;
            {
                const float* wrp = swr + sl*4096;
                const float* wip = swi + sl*4096;
                #pragma unroll 8
                for (int i = 0; i < 64; i++) {
                    float w_r = wrp[i*64 + o], w_i = wip[i*64 + o];
                    float f_r = fr[sl][i],     f_i = fi[sl][i];
                    accr = fmaf(f_r, w_r, accr); accr = fmaf(-f_i, w_i, accr);
                    acci = fmaf(f_r, w_i, acci); acci = fmaf( f_i, w_r, acci);
                }
            }
            __syncthreads();
            {
                float g0r = it ? gr[sl][o] : 0.f;
                float g0i = it ? gi[sl][o] : 0.f;
                gr[sl][o] = g0r + accr;
                gi[sl][o] = g0i + acci;
            }
            __syncthreads();
        }
        {
            int s = sl ? s1 : s0;
            int base = (b*CH + o)*64 + s*2;
            g_gA[base]   = gr[sl][o];
            g_gA[base+1] = gi[sl][o];
        }
    } else {
        int ih = sl;   // i-range half
        for (int it = 0; it < 6; it++) {
            if (ih == 0) {
                float tr = 0.f, ti = 0.f;
                if (it > 0) {
                    float grv = gr[0][o], giv = gi[0][o];
                    if      (tmode == 0) { tr = grv;       ti = giv; }
                    else if (tmode == 1) { tr = grv;       ti = 0.f; }
                    else                 { tr = 0.5f*grv;  ti = 0.5f*giv; }
                }
                fr[0][o] = vr[0][o] + tr;
                fi[0][o] = vi[0][o] + ti;
            }
            __syncthreads();
            float accr = 0.f, acci = 0.f;
            {
                int ib = ih * 32;
                #pragma unroll 8
                for (int i = ib; i < ib + 32; i++) {
                    float w_r = swr[i*64 + o], w_i = swi[i*64 + o];
                    float f_r = fr[0][i],      f_i = fi[0][i];
                    accr = fmaf(f_r, w_r, accr); accr = fmaf(-f_i, w_i, accr);
                    acci = fmaf(f_r, w_i, acci); acci = fmaf( f_i, w_r, acci);
                }
            }
            if (ih == 1) { pr[o] = accr; pi[o] = acci; }
            __syncthreads();
            if (ih == 0) {
                float g0r = it ? gr[0][o] : 0.f;
                float g0i = it ? gi[0][o] : 0.f;
                gr[0][o] = g0r + accr + pr[o];
                gi[0][o] = g0i + acci + pi[o];
            }
            __syncthreads();
        }
        if (ih == 0) {
            int base = (b*CH + o)*64 + s0*2;
            g_gA[base]   = gr[0][o];
            g_gA[base+1] = gi[0][o];
        }
    }
}

// ---------------------------------------------------------------------------
// K5: recon-once epilogue — R13 version VERBATIM (144 us measured best).
// ---------------------------------------------------------------------------
#define HVS_SMEM (64*128*8)

__global__ void __launch_bounds__(256, 2) k_final(
    const float* __restrict__ x,
    const float* __restrict__ ew, const float* __restrict__ eb,
    const float* __restrict__ d1w, const float* __restrict__ d1b,
    const float* __restrict__ d2w, const float* __restrict__ d2b,
    float* __restrict__ out)
{
    extern __shared__ u64 hvs[];     // [64][128] u64 = 64 KB dynamic
    __shared__ u64 zp[64*8];
    __shared__ float gm[4096];
    __shared__ float4 wenc[64];
    __shared__ u64 wp[64*32];
    __shared__ u64 b1p[32], w2p[32];
    __shared__ float pA[2][128], pB[2][128];

    int t = threadIdx.x, b = blockIdx.y;
    int hpair = blockIdx.x & 127, wtile = blockIdx.x >> 7;
    int wv = t & 127, oh = t >> 7;
    int h0 = hpair*2, h1 = h0 + 1;
    int w = wtile*128 + wv;

    for (int idx = t; idx < 2048; idx += 256) {
        int c = idx & 63, op = idx >> 6;
        wp[c*32 + op] = pk2(d1w[(2*op)*64 + c], d1w[(2*op+1)*64 + c]);
    }
    if (t < 32) {
        b1p[t] = pk2(d1b[2*t], d1b[2*t+1]);
        w2p[t] = pk2(d2w[2*t], d2w[2*t+1]);
    }
    if (t < 64) {
        const float K = 2.8853900817779268f;
        wenc[t] = make_float4(K*ew[3*t], K*ew[3*t+1], K*ew[3*t+2], K*eb[t]);
    }
    {
        const float4* gsrc = (const float4*)(g_gA + b*4096);
        float4* gdst = (float4*)gm;
        #pragma unroll
        for (int i = 0; i < 4; i++) gdst[t + i*256] = gsrc[t + i*256];
    }
    __syncthreads();

    {
        int c = t >> 2, ky = t & 3;
        float zrA = 0.f, ziA = 0.f, zrB = 0.f, ziB = 0.f;
        float aA = 6.28318530717958647692f * (1.0f/256.0f) * (float)h0;
        float c1A, s1A; sincosf(aA, &s1A, &c1A);
        float c2A = c1A*c1A - s1A*s1A,  s2A = 2.f*s1A*c1A;
        float c3A = c2A*c1A - s2A*s1A,  s3A = s2A*c1A + c2A*s1A;
        float c4A = c2A*c2A - s2A*s2A,  s4A = 2.f*s2A*c2A;
        float pcA[8] = {1.f, c1A, c2A, c3A,  c4A,  c3A,  c2A,  c1A};
        float psA[8] = {0.f, s1A, s2A, s3A, -s4A, -s3A, -s2A, -s1A};
        float aB = 6.28318530717958647692f * (1.0f/256.0f) * (float)h1;
        float c1B, s1B; sincosf(aB, &s1B, &c1B);
        float c2B = c1B*c1B - s1B*s1B,  s2B = 2.f*s1B*c1B;
        float c3B = c2B*c1B - s2B*s1B,  s3B = s2B*c1B + c2B*s1B;
        float c4B = c2B*c2B - s2B*s2B,  s4B = 2.f*s2B*c2B;
        float pcB[8] = {1.f, c1B, c2B, c3B,  c4B,  c3B,  c2B,  c1B};
        float psB[8] = {0.f, s1B, s2B, s3B, -s4B, -s3B, -s2B, -s1B};
        #pragma unroll
        for (int kxi = 0; kxi < 8; kxi++) {
            float grv = gm[c*64 + kxi*8 + ky*2];
            float giv = gm[c*64 + kxi*8 + ky*2 + 1];
            zrA += grv*pcA[kxi] - giv*psA[kxi];
            ziA += grv*psA[kxi] + giv*pcA[kxi];
            zrB += grv*pcB[kxi] - giv*psB[kxi];
            ziB += grv*psB[kxi] + giv*pcB[kxi];
        }
        if (ky == 0) {
            zp[c*8]     = pk2(zrA*(1.f/131072.f) + 2.f, zrB*(1.f/131072.f) + 2.f);
            zp[c*8 + 7] = 0ull;
        } else {
            zp[c*8 + ky*2 - 1] = pk2( zrA*(1.f/65536.f),  zrB*(1.f/65536.f));
            zp[c*8 + ky*2]     = pk2(-ziA*(1.f/65536.f), -ziB*(1.f/65536.f));
        }
    }
    __syncthreads();

    float a = 6.28318530717958647692f * (1.0f/256.0f) * (float)w;
    float cy1, sy1; sincosf(a, &sy1, &cy1);
    float cy2 = cy1*cy1 - sy1*sy1, sy2 = 2.f*sy1*cy1;
    float cy3 = cy2*cy1 - sy2*sy1, sy3 = sy2*cy1 + cy2*sy1;
    u64 C1 = splat2(cy1), S1 = splat2(sy1);
    u64 C2 = splat2(cy2), S2 = splat2(sy2);
    u64 C3 = splat2(cy3), S3 = splat2(sy3);
    u64 M4 = splat2(-4.f);

    const float* xpA = x + (b*3)*HW + h0*WW + w;
    float x0A = xpA[0],    x0B = xpA[WW];
    float x1A = xpA[HW],   x1B = xpA[HW+WW];
    float x2A = xpA[2*HW], x2B = xpA[2*HW+WW];

    // --- Phase 1: recon HALF the c range into hvs ---
    {
        int cbeg = oh * 32;
        const ulonglong2* zrow2 = (const ulonglong2*)zp;
        #pragma unroll 8
        for (int c = cbeg; c < cbeg + 32; c++) {
            float4 we = wenc[c];
            float preA = fmaf(we.x, x0A, fmaf(we.y, x1A, fmaf(we.z, x2A, we.w)));
            float preB = fmaf(we.x, x0B, fmaf(we.y, x1B, fmaf(we.z, x2B, we.w)));
            float eA, rA, eB, rB;
            asm("ex2.approx.f32 %0, %1;" : "=f"(eA) : "f"(preA));
            asm("ex2.approx.f32 %0, %1;" : "=f"(eB) : "f"(preB));
            asm("rcp.approx.f32 %0, %1;" : "=f"(rA) : "f"(eA + 1.0f));
            asm("rcp.approx.f32 %0, %1;" : "=f"(rB) : "f"(eB + 1.0f));
            ulonglong2 z01 = zrow2[c*4], z23 = zrow2[c*4+1], z45 = zrow2[c*4+2], z67 = zrow2[c*4+3];
            u64 hv2 = f2fma(pk2(rA, rB), M4, z01.x);
            hv2 = f2fma(z01.y, C1, hv2);
            hv2 = f2fma(z23.x, S1, hv2);
            hv2 = f2fma(z23.y, C2, hv2);
            hv2 = f2fma(z45.x, S2, hv2);
            hv2 = f2fma(z45.y, C3, hv2);
            hv2 = f2fma(z67.x, S3, hv2);
            hvs[c*128 + wv] = hv2;
        }
    }
    __syncthreads();

    // --- Phase 2: GEMV over all 64 c from hvs ---
    u64 accA[16], accB[16];
    #pragma unroll
    for (int k = 0; k < 16; k++) { u64 bb = b1p[oh*16 + k]; accA[k] = bb; accB[k] = bb; }

    const ulonglong2* wrow = (const ulonglong2*)&wp[oh*16];
    #pragma unroll 8
    for (int c = 0; c < 64; c++) {
        u64 hv2 = hvs[c*128 + wv];
        float2 hv = upk2(hv2);
        u64 hsA = splat2(hv.x), hsB = splat2(hv.y);
        const ulonglong2* wr = wrow + c*16;
        #pragma unroll
        for (int k2 = 0; k2 < 8; k2++) {
            ulonglong2 wv2 = wr[k2];
            accA[k2*2]   = f2fma(hsA, wv2.x, accA[k2*2]);
            accA[k2*2+1] = f2fma(hsA, wv2.y, accA[k2*2+1]);
            accB[k2*2]   = f2fma(hsB, wv2.x, accB[k2*2]);
            accB[k2*2+1] = f2fma(hsB, wv2.y, accB[k2*2+1]);
        }
    }

    u64 oaccA = 0ull, oaccB = 0ull;
    #pragma unroll
    for (int k = 0; k < 16; k++) {
        u64 w2v = w2p[oh*16 + k];
        float2 vA = upk2(accA[k]);
        float2 vB = upk2(accB[k]);
        oaccA = f2fma(pk2(fast_tanh(vA.x), fast_tanh(vA.y)), w2v, oaccA);
        oaccB = f2fma(pk2(fast_tanh(vB.x), fast_tanh(vB.y)), w2v, oaccB);
    }
    float2 oA = upk2(oaccA), oB = upk2(oaccB);
    pA[oh][wv] = oA.x + oA.y;
    pB[oh][wv] = oB.x + oB.y;
    __syncthreads();

    float b2v = d2b[0];
    if (oh == 0) {
        out[b*HW + h0*WW + w] = pA[0][wv] + pA[1][wv] + b2v;
    } else {
        out[b*HW + h1*WW + w] = pB[0][wv] + pB[1][wv] + b2v;
    }
}

extern "C" void kernel_launch(void* const* d_in, const int* in_sizes, int n_in,
                              void* d_out, int out_size)
{
    const float* x   = (const float*)d_in[0];
    const float* ew  = (const float*)d_in[1];
    const float* eb  = (const float*)d_in[2];
    const float* d1w = (const float*)d_in[3];
    const float* d1b = (const float*)d_in[4];
    const float* d2w = (const float*)d_in[5];
    const float* d2b = (const float*)d_in[6];
    const float* w1r = (const float*)d_in[7];
    const float* w1i = (const float*)d_in[8];
    const float* w2r = (const float*)d_in[9];
    const float* w2i = (const float*)d_in[10];
    float* out = (float*)d_out;

    cudaFuncSetAttribute(k_mix6, cudaFuncAttributeMaxDynamicSharedMemorySize, 65536);
    cudaFuncSetAttribute(k_final, cudaFuncAttributeMaxDynamicSharedMemorySize, HVS_SMEM);

    k_repack<<<32, 256>>>(w1r, w1i, w2r, w2i);
    k_project<<<dim3(32, 8), 256>>>(x, ew, eb);
    k_mix6<<<dim3(29, 8), 128, 65536>>>();
    k_final<<<dim3(256, 8), 256, HVS_SMEM>>>(x, ew, eb, d1w, d1b, d2w, d2b, out);
}